// round 1
// baseline (speedup 1.0000x reference)
#include <cuda_runtime.h>
#include <cuda_bf16.h>
#include <math_constants.h>

// Problem constants
#define BB 2
#define CC 1024
#define LL 2048
#define HH 16
#define HD 64
#define BCL (BB*CC*LL)               // 4,194,304 floats
#define NBH (BB*HH)                   // 32
#define SROWS ((size_t)NBH * LL)      // 65536
#define SELEMS (SROWS * LL)           // 134,217,728 floats (512 MB)

// Scratch (device globals — runtime allocation is forbidden)
__device__ float g_K [BCL];
__device__ float g_Q [BCL];
__device__ float g_AO[BCL];
__device__ float g_Y [BCL];
__device__ float g_T [BCL];
__device__ float g_S [SELEMS];

// ---------------------------------------------------------------------------
// conv1x1: Out[b,o,l] = sum_c W[o,c] * X[b,c,l] + bias[o]  (+A1 +A2, relu opt)
// 64(o) x 64(l) block tile, K-tile 16, 256 threads, 4x4 per thread.
// ---------------------------------------------------------------------------
template<bool RELU, int NADD>
__global__ __launch_bounds__(256)
void conv1x1_kernel(const float* __restrict__ W, const float* __restrict__ bias,
                    const float* __restrict__ X, float* __restrict__ Out,
                    const float* __restrict__ A1, const float* __restrict__ A2)
{
    const int b  = blockIdx.z;
    const int o0 = blockIdx.y * 64;
    const int l0 = blockIdx.x * 64;
    const float* Xb = X + (size_t)b * CC * LL;
    float* Ob = Out + (size_t)b * CC * LL;

    __shared__ float sW[16][65];   // [c][o], padded
    __shared__ float sX[16][64];   // [c][l]

    const int tid = threadIdx.x;
    const int tx = tid & 15;       // 0..15 -> l group
    const int ty = tid >> 4;       // 0..15 -> o group

    float acc[4][4] = {};

    for (int c0 = 0; c0 < CC; c0 += 16) {
        // Load W tile: sW[c][o]
        {
            const int c = tid & 15;
            const int o = tid >> 4;        // 0..15
            #pragma unroll
            for (int p = 0; p < 4; p++)
                sW[c][o + p * 16] = W[(size_t)(o0 + o + p * 16) * CC + c0 + c];
        }
        // Load X tile: sX[c][l]
        {
            const int l = tid & 63;
            const int c = tid >> 6;        // 0..3
            #pragma unroll
            for (int p = 0; p < 4; p++)
                sX[c + p * 4][l] = Xb[(size_t)(c0 + c + p * 4) * LL + l0 + l];
        }
        __syncthreads();

        #pragma unroll
        for (int k = 0; k < 16; k++) {
            float a[4], bv[4];
            #pragma unroll
            for (int i = 0; i < 4; i++) a[i]  = sW[k][ty * 4 + i];
            #pragma unroll
            for (int j = 0; j < 4; j++) bv[j] = sX[k][tx + j * 16];
            #pragma unroll
            for (int i = 0; i < 4; i++)
                #pragma unroll
                for (int j = 0; j < 4; j++)
                    acc[i][j] = fmaf(a[i], bv[j], acc[i][j]);
        }
        __syncthreads();
    }

    const size_t boff = (size_t)b * CC * LL;
    #pragma unroll
    for (int i = 0; i < 4; i++) {
        const int o = o0 + ty * 4 + i;
        const float bvv = bias[o];
        #pragma unroll
        for (int j = 0; j < 4; j++) {
            const int l = l0 + tx + j * 16;
            const size_t idx = (size_t)o * LL + l;
            float v = acc[i][j] + bvv;
            if (RELU) v = fmaxf(v, 0.0f);
            if (NADD >= 1) v += A1[boff + idx];
            if (NADD >= 2) v += A2[boff + idx];
            Ob[idx] = v;
        }
    }
}

// ---------------------------------------------------------------------------
// scores: S[bh,l,m] = (1/1024) * sum_{c<64} K[bh,c,l] * Q[bh,c,m]
// 64x64 output tile per block, full K=64 reduction, 256 threads, 4x4/thread.
// ---------------------------------------------------------------------------
__global__ __launch_bounds__(256)
void scores_kernel(const float* __restrict__ K, const float* __restrict__ Q,
                   float* __restrict__ S)
{
    const int bh = blockIdx.z;
    const int b = bh >> 4, h = bh & 15;
    const int l0 = blockIdx.y * 64;
    const int m0 = blockIdx.x * 64;

    const size_t hoff = (size_t)b * CC * LL + (size_t)h * HD * LL;
    const float* Kb = K + hoff;
    const float* Qb = Q + hoff;
    float* Sb = S + (size_t)bh * LL * LL;

    __shared__ float sK[64][65];
    __shared__ float sQ[64][65];

    const int tid = threadIdx.x;
    const int tx = tid & 15, ty = tid >> 4;

    {
        const int col = tid & 63;
        const int row = tid >> 6;     // 0..3
        #pragma unroll
        for (int p = 0; p < 16; p++) {
            sK[row + p * 4][col] = Kb[(size_t)(row + p * 4) * LL + l0 + col];
            sQ[row + p * 4][col] = Qb[(size_t)(row + p * 4) * LL + m0 + col];
        }
    }
    __syncthreads();

    float acc[4][4] = {};
    #pragma unroll 16
    for (int k = 0; k < 64; k++) {
        float a[4], bv[4];
        #pragma unroll
        for (int i = 0; i < 4; i++) a[i]  = sK[k][ty * 4 + i];
        #pragma unroll
        for (int j = 0; j < 4; j++) bv[j] = sQ[k][tx + j * 16];
        #pragma unroll
        for (int i = 0; i < 4; i++)
            #pragma unroll
            for (int j = 0; j < 4; j++)
                acc[i][j] = fmaf(a[i], bv[j], acc[i][j]);
    }

    const float scale = 1.0f / 1024.0f;   // softmax(scores / (L/2))
    #pragma unroll
    for (int i = 0; i < 4; i++) {
        const size_t rowo = (size_t)(l0 + ty * 4 + i) * LL;
        #pragma unroll
        for (int j = 0; j < 4; j++)
            Sb[rowo + m0 + tx + j * 16] = acc[i][j] * scale;
    }
}

// ---------------------------------------------------------------------------
// softmax over last axis (2048), one block (256 thr) per row, in place
// ---------------------------------------------------------------------------
__device__ __forceinline__ float warp_rmax(float v) {
    #pragma unroll
    for (int o = 16; o > 0; o >>= 1) v = fmaxf(v, __shfl_xor_sync(0xffffffffu, v, o));
    return v;
}
__device__ __forceinline__ float warp_rsum(float v) {
    #pragma unroll
    for (int o = 16; o > 0; o >>= 1) v += __shfl_xor_sync(0xffffffffu, v, o);
    return v;
}

__global__ __launch_bounds__(256)
void softmax_kernel(float* __restrict__ S)
{
    const size_t row = blockIdx.x;
    float* p = S + row * LL;
    const int tid = threadIdx.x;
    const int lane = tid & 31, wid = tid >> 5;

    float4 v0 = reinterpret_cast<float4*>(p)[tid];
    float4 v1 = reinterpret_cast<float4*>(p)[tid + 256];

    float m = fmaxf(fmaxf(fmaxf(v0.x, v0.y), fmaxf(v0.z, v0.w)),
                    fmaxf(fmaxf(v1.x, v1.y), fmaxf(v1.z, v1.w)));

    __shared__ float sred[8];
    __shared__ float sbroad;

    m = warp_rmax(m);
    if (lane == 0) sred[wid] = m;
    __syncthreads();
    if (tid == 0) {
        float t = sred[0];
        #pragma unroll
        for (int i = 1; i < 8; i++) t = fmaxf(t, sred[i]);
        sbroad = t;
    }
    __syncthreads();
    const float mx = sbroad;
    __syncthreads();

    v0.x = __expf(v0.x - mx); v0.y = __expf(v0.y - mx);
    v0.z = __expf(v0.z - mx); v0.w = __expf(v0.w - mx);
    v1.x = __expf(v1.x - mx); v1.y = __expf(v1.y - mx);
    v1.z = __expf(v1.z - mx); v1.w = __expf(v1.w - mx);

    float s = (v0.x + v0.y + v0.z + v0.w) + (v1.x + v1.y + v1.z + v1.w);
    s = warp_rsum(s);
    if (lane == 0) sred[wid] = s;
    __syncthreads();
    if (tid == 0) {
        float t = 0.0f;
        #pragma unroll
        for (int i = 0; i < 8; i++) t += sred[i];
        sbroad = t;
    }
    __syncthreads();
    const float inv = 1.0f / sbroad;

    v0.x *= inv; v0.y *= inv; v0.z *= inv; v0.w *= inv;
    v1.x *= inv; v1.y *= inv; v1.z *= inv; v1.w *= inv;
    reinterpret_cast<float4*>(p)[tid]       = v0;
    reinterpret_cast<float4*>(p)[tid + 256] = v1;
}

// ---------------------------------------------------------------------------
// AV: O[bh,c,m] = sum_l X[bh,c,l] * A[bh,l,m]   (c<64, full hd per block)
// 64(c) x 64(m) per block, loop l in tiles of 64.
// ---------------------------------------------------------------------------
__global__ __launch_bounds__(256)
void av_kernel(const float* __restrict__ X, const float* __restrict__ A,
               float* __restrict__ O)
{
    const int bh = blockIdx.y;
    const int b = bh >> 4, h = bh & 15;
    const int m0 = blockIdx.x * 64;

    const size_t hoff = (size_t)b * CC * LL + (size_t)h * HD * LL;
    const float* Xb = X + hoff;
    const float* Ab = A + (size_t)bh * LL * LL;
    float* Ob = O + hoff;

    __shared__ float sX[64][65];   // [c][l]
    __shared__ float sA[64][65];   // [l][m]

    const int tid = threadIdx.x;
    const int tx = tid & 15, ty = tid >> 4;

    float acc[4][4] = {};

    for (int l0 = 0; l0 < LL; l0 += 64) {
        const int col = tid & 63;
        const int row = tid >> 6;    // 0..3
        #pragma unroll
        for (int p = 0; p < 16; p++) {
            sX[row + p * 4][col] = Xb[(size_t)(row + p * 4) * LL + l0 + col];
            sA[row + p * 4][col] = Ab[(size_t)(l0 + row + p * 4) * LL + m0 + col];
        }
        __syncthreads();

        #pragma unroll 16
        for (int k = 0; k < 64; k++) {
            float a[4], bv[4];
            #pragma unroll
            for (int i = 0; i < 4; i++) a[i]  = sX[ty * 4 + i][k];
            #pragma unroll
            for (int j = 0; j < 4; j++) bv[j] = sA[k][tx + j * 16];
            #pragma unroll
            for (int i = 0; i < 4; i++)
                #pragma unroll
                for (int j = 0; j < 4; j++)
                    acc[i][j] = fmaf(a[i], bv[j], acc[i][j]);
        }
        __syncthreads();
    }

    #pragma unroll
    for (int i = 0; i < 4; i++) {
        const size_t rowo = (size_t)(ty * 4 + i) * LL;
        #pragma unroll
        for (int j = 0; j < 4; j++)
            Ob[rowo + m0 + tx + j * 16] = acc[i][j];
    }
}

// ---------------------------------------------------------------------------
extern "C" void kernel_launch(void* const* d_in, const int* in_sizes, int n_in,
                              void* d_out, int out_size)
{
    const float* x   = (const float*)d_in[0];
    const float* kw  = (const float*)d_in[1];
    const float* kb  = (const float*)d_in[2];
    const float* qw  = (const float*)d_in[3];
    const float* qb  = (const float*)d_in[4];
    const float* pw  = (const float*)d_in[5];
    const float* pb  = (const float*)d_in[6];
    const float* c1w = (const float*)d_in[7];
    const float* c1b = (const float*)d_in[8];
    const float* c2w = (const float*)d_in[9];
    const float* c2b = (const float*)d_in[10];
    float* out = (float*)d_out;

    float *gK, *gQ, *gS, *gAO, *gY, *gT;
    cudaGetSymbolAddress((void**)&gK,  g_K);
    cudaGetSymbolAddress((void**)&gQ,  g_Q);
    cudaGetSymbolAddress((void**)&gS,  g_S);
    cudaGetSymbolAddress((void**)&gAO, g_AO);
    cudaGetSymbolAddress((void**)&gY,  g_Y);
    cudaGetSymbolAddress((void**)&gT,  g_T);

    dim3 cgrid(LL / 64, CC / 64, BB);   // (32,16,2)
    dim3 cblk(256);

    // K and Q projections
    conv1x1_kernel<false, 0><<<cgrid, cblk>>>(kw, kb, x, gK, nullptr, nullptr);
    conv1x1_kernel<false, 0><<<cgrid, cblk>>>(qw, qb, x, gQ, nullptr, nullptr);

    // scores (scaled) -> softmax -> attention-weighted values
    scores_kernel<<<dim3(LL / 64, LL / 64, NBH), 256>>>(gK, gQ, gS);
    softmax_kernel<<<(unsigned)SROWS, 256>>>(gS);
    av_kernel<<<dim3(LL / 64, NBH), 256>>>(x, gS, gAO);

    // y = pconv(attn_out) + x
    conv1x1_kernel<false, 1><<<cgrid, cblk>>>(pw, pb, gAO, gY, x, nullptr);
    // t = relu(c1(y))
    conv1x1_kernel<true, 0><<<cgrid, cblk>>>(c1w, c1b, gY, gT, nullptr, nullptr);
    // out = c2(t) + y + x
    conv1x1_kernel<false, 2><<<cgrid, cblk>>>(c2w, c2b, gT, out, gY, x);
}

// round 2
// speedup vs baseline: 1.0018x; 1.0018x over previous
#include <cuda_runtime.h>
#include <cuda_bf16.h>
#include <math_constants.h>

// Problem constants
#define BB 2
#define CC 1024
#define LL 2048
#define HH 16
#define HD 64
#define BCL (BB*CC*LL)               // 4,194,304 floats
#define NBH (BB*HH)                   // 32
#define SROWS ((size_t)NBH * LL)      // 65536
#define SELEMS (SROWS * LL)           // 134,217,728 floats (512 MB)

// Scratch (device globals — runtime allocation is forbidden)
__device__ float g_K [BCL];
__device__ float g_Q [BCL];
__device__ float g_AO[BCL];
__device__ float g_Y [BCL];
__device__ float g_T [BCL];
__device__ float g_S [SELEMS];

// ---------------------------------------------------------------------------
// conv1x1: Out[b,o,l] = sum_c W[o,c] * X[b,c,l] + bias[o]  (+A1 +A2, relu opt)
// 64(o) x 64(l) block tile, K-tile 16, 256 threads, 4x4 per thread.
// ---------------------------------------------------------------------------
template<bool RELU, int NADD>
__global__ __launch_bounds__(256)
void conv1x1_kernel(const float* __restrict__ W, const float* __restrict__ bias,
                    const float* __restrict__ X, float* __restrict__ Out,
                    const float* __restrict__ A1, const float* __restrict__ A2)
{
    const int b  = blockIdx.z;
    const int o0 = blockIdx.y * 64;
    const int l0 = blockIdx.x * 64;
    const float* Xb = X + (size_t)b * CC * LL;
    float* Ob = Out + (size_t)b * CC * LL;

    __shared__ float sW[16][65];   // [c][o], padded
    __shared__ float sX[16][64];   // [c][l]

    const int tid = threadIdx.x;
    const int tx = tid & 15;       // 0..15 -> l group
    const int ty = tid >> 4;       // 0..15 -> o group

    float acc[4][4] = {};

    for (int c0 = 0; c0 < CC; c0 += 16) {
        // Load W tile: sW[c][o]
        {
            const int c = tid & 15;
            const int o = tid >> 4;        // 0..15
            #pragma unroll
            for (int p = 0; p < 4; p++)
                sW[c][o + p * 16] = W[(size_t)(o0 + o + p * 16) * CC + c0 + c];
        }
        // Load X tile: sX[c][l]
        {
            const int l = tid & 63;
            const int c = tid >> 6;        // 0..3
            #pragma unroll
            for (int p = 0; p < 4; p++)
                sX[c + p * 4][l] = Xb[(size_t)(c0 + c + p * 4) * LL + l0 + l];
        }
        __syncthreads();

        #pragma unroll
        for (int k = 0; k < 16; k++) {
            float a[4], bv[4];
            #pragma unroll
            for (int i = 0; i < 4; i++) a[i]  = sW[k][ty * 4 + i];
            #pragma unroll
            for (int j = 0; j < 4; j++) bv[j] = sX[k][tx + j * 16];
            #pragma unroll
            for (int i = 0; i < 4; i++)
                #pragma unroll
                for (int j = 0; j < 4; j++)
                    acc[i][j] = fmaf(a[i], bv[j], acc[i][j]);
        }
        __syncthreads();
    }

    const size_t boff = (size_t)b * CC * LL;
    #pragma unroll
    for (int i = 0; i < 4; i++) {
        const int o = o0 + ty * 4 + i;
        const float bvv = bias[o];
        #pragma unroll
        for (int j = 0; j < 4; j++) {
            const int l = l0 + tx + j * 16;
            const size_t idx = (size_t)o * LL + l;
            float v = acc[i][j] + bvv;
            if (RELU) v = fmaxf(v, 0.0f);
            if (NADD >= 1) v += A1[boff + idx];
            if (NADD >= 2) v += A2[boff + idx];
            Ob[idx] = v;
        }
    }
}

// ---------------------------------------------------------------------------
// scores: S[bh,l,m] = (1/1024) * sum_{c<64} K[bh,c,l] * Q[bh,c,m]
// 64x64 output tile per block, full K=64 reduction, 256 threads, 4x4/thread.
// ---------------------------------------------------------------------------
__global__ __launch_bounds__(256)
void scores_kernel(const float* __restrict__ K, const float* __restrict__ Q,
                   float* __restrict__ S)
{
    const int bh = blockIdx.z;
    const int b = bh >> 4, h = bh & 15;
    const int l0 = blockIdx.y * 64;
    const int m0 = blockIdx.x * 64;

    const size_t hoff = (size_t)b * CC * LL + (size_t)h * HD * LL;
    const float* Kb = K + hoff;
    const float* Qb = Q + hoff;
    float* Sb = S + (size_t)bh * LL * LL;

    __shared__ float sK[64][65];
    __shared__ float sQ[64][65];

    const int tid = threadIdx.x;
    const int tx = tid & 15, ty = tid >> 4;

    {
        const int col = tid & 63;
        const int row = tid >> 6;     // 0..3
        #pragma unroll
        for (int p = 0; p < 16; p++) {
            sK[row + p * 4][col] = Kb[(size_t)(row + p * 4) * LL + l0 + col];
            sQ[row + p * 4][col] = Qb[(size_t)(row + p * 4) * LL + m0 + col];
        }
    }
    __syncthreads();

    float acc[4][4] = {};
    #pragma unroll 16
    for (int k = 0; k < 64; k++) {
        float a[4], bv[4];
        #pragma unroll
        for (int i = 0; i < 4; i++) a[i]  = sK[k][ty * 4 + i];
        #pragma unroll
        for (int j = 0; j < 4; j++) bv[j] = sQ[k][tx + j * 16];
        #pragma unroll
        for (int i = 0; i < 4; i++)
            #pragma unroll
            for (int j = 0; j < 4; j++)
                acc[i][j] = fmaf(a[i], bv[j], acc[i][j]);
    }

    const float scale = 1.0f / 1024.0f;   // softmax(scores / (L/2))
    #pragma unroll
    for (int i = 0; i < 4; i++) {
        const size_t rowo = (size_t)(l0 + ty * 4 + i) * LL;
        #pragma unroll
        for (int j = 0; j < 4; j++)
            Sb[rowo + m0 + tx + j * 16] = acc[i][j] * scale;
    }
}

// ---------------------------------------------------------------------------
// softmax over last axis (2048), one block (256 thr) per row, in place
// ---------------------------------------------------------------------------
__device__ __forceinline__ float warp_rmax(float v) {
    #pragma unroll
    for (int o = 16; o > 0; o >>= 1) v = fmaxf(v, __shfl_xor_sync(0xffffffffu, v, o));
    return v;
}
__device__ __forceinline__ float warp_rsum(float v) {
    #pragma unroll
    for (int o = 16; o > 0; o >>= 1) v += __shfl_xor_sync(0xffffffffu, v, o);
    return v;
}

__global__ __launch_bounds__(256)
void softmax_kernel(float* __restrict__ S)
{
    const size_t row = blockIdx.x;
    float* p = S + row * LL;
    const int tid = threadIdx.x;
    const int lane = tid & 31, wid = tid >> 5;

    float4 v0 = reinterpret_cast<float4*>(p)[tid];
    float4 v1 = reinterpret_cast<float4*>(p)[tid + 256];

    float m = fmaxf(fmaxf(fmaxf(v0.x, v0.y), fmaxf(v0.z, v0.w)),
                    fmaxf(fmaxf(v1.x, v1.y), fmaxf(v1.z, v1.w)));

    __shared__ float sred[8];
    __shared__ float sbroad;

    m = warp_rmax(m);
    if (lane == 0) sred[wid] = m;
    __syncthreads();
    if (tid == 0) {
        float t = sred[0];
        #pragma unroll
        for (int i = 1; i < 8; i++) t = fmaxf(t, sred[i]);
        sbroad = t;
    }
    __syncthreads();
    const float mx = sbroad;
    __syncthreads();

    v0.x = __expf(v0.x - mx); v0.y = __expf(v0.y - mx);
    v0.z = __expf(v0.z - mx); v0.w = __expf(v0.w - mx);
    v1.x = __expf(v1.x - mx); v1.y = __expf(v1.y - mx);
    v1.z = __expf(v1.z - mx); v1.w = __expf(v1.w - mx);

    float s = (v0.x + v0.y + v0.z + v0.w) + (v1.x + v1.y + v1.z + v1.w);
    s = warp_rsum(s);
    if (lane == 0) sred[wid] = s;
    __syncthreads();
    if (tid == 0) {
        float t = 0.0f;
        #pragma unroll
        for (int i = 0; i < 8; i++) t += sred[i];
        sbroad = t;
    }
    __syncthreads();
    const float inv = 1.0f / sbroad;

    v0.x *= inv; v0.y *= inv; v0.z *= inv; v0.w *= inv;
    v1.x *= inv; v1.y *= inv; v1.z *= inv; v1.w *= inv;
    reinterpret_cast<float4*>(p)[tid]       = v0;
    reinterpret_cast<float4*>(p)[tid + 256] = v1;
}

// ---------------------------------------------------------------------------
// AV: O[bh,c,m] = sum_l X[bh,c,l] * A[bh,l,m]   (c<64, full hd per block)
// 64(c) x 64(m) per block, loop l in tiles of 64.
// ---------------------------------------------------------------------------
__global__ __launch_bounds__(256)
void av_kernel(const float* __restrict__ X, const float* __restrict__ A,
               float* __restrict__ O)
{
    const int bh = blockIdx.y;
    const int b = bh >> 4, h = bh & 15;
    const int m0 = blockIdx.x * 64;

    const size_t hoff = (size_t)b * CC * LL + (size_t)h * HD * LL;
    const float* Xb = X + hoff;
    const float* Ab = A + (size_t)bh * LL * LL;
    float* Ob = O + hoff;

    __shared__ float sX[64][65];   // [c][l]
    __shared__ float sA[64][65];   // [l][m]

    const int tid = threadIdx.x;
    const int tx = tid & 15, ty = tid >> 4;

    float acc[4][4] = {};

    for (int l0 = 0; l0 < LL; l0 += 64) {
        const int col = tid & 63;
        const int row = tid >> 6;    // 0..3
        #pragma unroll
        for (int p = 0; p < 16; p++) {
            sX[row + p * 4][col] = Xb[(size_t)(row + p * 4) * LL + l0 + col];
            sA[row + p * 4][col] = Ab[(size_t)(l0 + row + p * 4) * LL + m0 + col];
        }
        __syncthreads();

        #pragma unroll 16
        for (int k = 0; k < 64; k++) {
            float a[4], bv[4];
            #pragma unroll
            for (int i = 0; i < 4; i++) a[i]  = sX[ty * 4 + i][k];
            #pragma unroll
            for (int j = 0; j < 4; j++) bv[j] = sA[k][tx + j * 16];
            #pragma unroll
            for (int i = 0; i < 4; i++)
                #pragma unroll
                for (int j = 0; j < 4; j++)
                    acc[i][j] = fmaf(a[i], bv[j], acc[i][j]);
        }
        __syncthreads();
    }

    #pragma unroll
    for (int i = 0; i < 4; i++) {
        const size_t rowo = (size_t)(ty * 4 + i) * LL;
        #pragma unroll
        for (int j = 0; j < 4; j++)
            Ob[rowo + m0 + tx + j * 16] = acc[i][j];
    }
}

// ---------------------------------------------------------------------------
extern "C" void kernel_launch(void* const* d_in, const int* in_sizes, int n_in,
                              void* d_out, int out_size)
{
    const float* x   = (const float*)d_in[0];
    const float* kw  = (const float*)d_in[1];
    const float* kb  = (const float*)d_in[2];
    const float* qw  = (const float*)d_in[3];
    const float* qb  = (const float*)d_in[4];
    const float* pw  = (const float*)d_in[5];
    const float* pb  = (const float*)d_in[6];
    const float* c1w = (const float*)d_in[7];
    const float* c1b = (const float*)d_in[8];
    const float* c2w = (const float*)d_in[9];
    const float* c2b = (const float*)d_in[10];
    float* out = (float*)d_out;

    float *gK, *gQ, *gS, *gAO, *gY, *gT;
    cudaGetSymbolAddress((void**)&gK,  g_K);
    cudaGetSymbolAddress((void**)&gQ,  g_Q);
    cudaGetSymbolAddress((void**)&gS,  g_S);
    cudaGetSymbolAddress((void**)&gAO, g_AO);
    cudaGetSymbolAddress((void**)&gY,  g_Y);
    cudaGetSymbolAddress((void**)&gT,  g_T);

    dim3 cgrid(LL / 64, CC / 64, BB);   // (32,16,2)
    dim3 cblk(256);

    // K and Q projections
    conv1x1_kernel<false, 0><<<cgrid, cblk>>>(kw, kb, x, gK, nullptr, nullptr);
    conv1x1_kernel<false, 0><<<cgrid, cblk>>>(qw, qb, x, gQ, nullptr, nullptr);

    // scores (scaled) -> softmax -> attention-weighted values
    scores_kernel<<<dim3(LL / 64, LL / 64, NBH), 256>>>(gK, gQ, gS);
    softmax_kernel<<<(unsigned)SROWS, 256>>>(gS);
    av_kernel<<<dim3(LL / 64, NBH), 256>>>(x, gS, gAO);

    // y = pconv(attn_out) + x
    conv1x1_kernel<false, 1><<<cgrid, cblk>>>(pw, pb, gAO, gY, x, nullptr);
    // t = relu(c1(y))
    conv1x1_kernel<true, 0><<<cgrid, cblk>>>(c1w, c1b, gY, gT, nullptr, nullptr);
    // out = c2(t) + y + x
    conv1x1_kernel<false, 2><<<cgrid, cblk>>>(c2w, c2b, gT, out, gY, x);
}